// round 1
// baseline (speedup 1.0000x reference)
#include <cuda_runtime.h>

// Problem constants (match reference)
#define MASK_P   0.15f
#define MASK_LEN 8
#define B_DIM    64
#define H_DIM    512
#define W_DIM    256
#define C_DIM    4

// x:         [B, H, W, C] f32
// time_rand: [B, MASK_LEN, W, C] f32
// freq_rand: [B, H, MASK_LEN, C] f32
// time_starts: [B] i32
// freq_starts: [B] i32
// out = x * mask[None], mask[h,w,c] = prod_b(1 - padded_t) * prod_b(1 - padded_f)

__global__ __launch_bounds__(256, 4)
void masking_kernel(const float4* __restrict__ x,
                    const float4* __restrict__ time_rand,   // [B,8,W] of float4 (C packed)
                    const float4* __restrict__ freq_rand,   // [B,H,8] of float4
                    const int*    __restrict__ time_starts,
                    const int*    __restrict__ freq_starts,
                    float4*       __restrict__ out)
{
    __shared__ int s_ts[B_DIM];
    __shared__ int s_fs[B_DIM];

    if (threadIdx.x < B_DIM) {
        s_ts[threadIdx.x] = time_starts[threadIdx.x];
        s_fs[threadIdx.x] = freq_starts[threadIdx.x];
    }
    __syncthreads();

    const int tid = blockIdx.x * blockDim.x + threadIdx.x;   // one per (h, w)
    const int w = tid & (W_DIM - 1);
    const int h = tid >> 8;                                  // W_DIM = 256

    // ---- Phase 1: build the 4-channel mask for this (h, w) pixel ----
    float4 m = make_float4(1.f, 1.f, 1.f, 1.f);

    #pragma unroll 4
    for (int b = 0; b < B_DIM; ++b) {
        // time mask contribution: strip of 8 rows starting at ts[b]
        int lt = h - s_ts[b];
        if ((unsigned)lt < (unsigned)MASK_LEN) {
            float4 tr = __ldg(&time_rand[(b * MASK_LEN + lt) * W_DIM + w]);
            if (tr.x < MASK_P) m.x = 0.f;
            if (tr.y < MASK_P) m.y = 0.f;
            if (tr.z < MASK_P) m.z = 0.f;
            if (tr.w < MASK_P) m.w = 0.f;
        }
        // freq mask contribution: strip of 8 cols starting at fs[b]
        int lf = w - s_fs[b];
        if ((unsigned)lf < (unsigned)MASK_LEN) {
            float4 fr = __ldg(&freq_rand[(b * H_DIM + h) * MASK_LEN + lf]);
            if (fr.x < MASK_P) m.x = 0.f;
            if (fr.y < MASK_P) m.y = 0.f;
            if (fr.z < MASK_P) m.z = 0.f;
            if (fr.w < MASK_P) m.w = 0.f;
        }
    }

    // ---- Phase 2: stream all 64 batches through this pixel ----
    const int pix = h * W_DIM + w;           // index in float4 units
    const int HW  = H_DIM * W_DIM;

    #pragma unroll 8
    for (int b = 0; b < B_DIM; ++b) {
        float4 v = x[b * HW + pix];
        v.x *= m.x; v.y *= m.y; v.z *= m.z; v.w *= m.w;
        out[b * HW + pix] = v;
    }
}

extern "C" void kernel_launch(void* const* d_in, const int* in_sizes, int n_in,
                              void* d_out, int out_size)
{
    const float4* x    = (const float4*)d_in[0];
    const float4* tr   = (const float4*)d_in[1];
    const float4* fr   = (const float4*)d_in[2];
    const int*    ts   = (const int*)d_in[3];
    const int*    fs   = (const int*)d_in[4];
    float4*       out  = (float4*)d_out;

    const int pixels = H_DIM * W_DIM;        // 131072 threads, one per (h,w)
    dim3 block(256);
    dim3 grid(pixels / 256);                 // 512 blocks
    masking_kernel<<<grid, block>>>(x, tr, fr, ts, fs, out);
}